// round 4
// baseline (speedup 1.0000x reference)
#include <cuda_runtime.h>

#define NN 50000
#define NE 800000
#define INF 96
#define HF  256
#define NC  40

// ---------------- scratch (__device__ globals; no allocations) ----------------
__device__ float g_deg_out[NN];
__device__ float g_deg_in[NN];
__device__ float g_nout[NN];   // rsqrt(max(deg_out,1))
__device__ float g_nin[NN];    // rsqrt(max(deg_in,1))
__device__ __align__(16) float g_agg1[NN * INF];  // edge-aggregated x*nout
__device__ __align__(16) float g_h[NN * HF];      // relu(layer1)*nout  (layer2 input)
__device__ __align__(16) float g_p[NN * NC];      // g_h @ W2

__device__ __forceinline__ void red_add_v4(float4* a, float4 v) {
    asm volatile("red.global.add.v4.f32 [%0], {%1,%2,%3,%4};"
                 :: "l"(a), "f"(v.x), "f"(v.y), "f"(v.z), "f"(v.w) : "memory");
}
__device__ __forceinline__ void red_add_f32(float* a, float v) {
    asm volatile("red.global.add.f32 [%0], %1;" :: "l"(a), "f"(v) : "memory");
}

// ---------------- kernels ----------------

// zero degree counters, agg1 scratch, and d_out (scatter target for layer 2)
__global__ void k_zero(float4* __restrict__ out4) {
    int stride = gridDim.x * blockDim.x;
    int i0 = blockIdx.x * blockDim.x + threadIdx.x;
    for (int i = i0; i < NN; i += stride) { g_deg_out[i] = 0.f; g_deg_in[i] = 0.f; }
    float4 z = make_float4(0.f, 0.f, 0.f, 0.f);
    float4* a1 = (float4*)g_agg1;
    for (int i = i0; i < NN * INF / 4; i += stride) a1[i] = z;
    for (int i = i0; i < NN * NC / 4; i += stride) out4[i] = z;
}

__global__ void k_deg(const int* __restrict__ src, const int* __restrict__ dst) {
    int e = blockIdx.x * blockDim.x + threadIdx.x;
    if (e < NE) {
        red_add_f32(&g_deg_out[src[e]], 1.f);
        red_add_f32(&g_deg_in[dst[e]], 1.f);
    }
}

__global__ void k_norm() {
    int i = blockIdx.x * blockDim.x + threadIdx.x;
    if (i < NN) {
        g_nout[i] = rsqrtf(fmaxf(g_deg_out[i], 1.f));
        g_nin[i]  = rsqrtf(fmaxf(g_deg_in[i], 1.f));
    }
}

// layer-1 aggregation with folded source scaling:
// for each (edge, float4-chunk): agg1[dst] += x[src] * nout[src]
__global__ void k_agg1(const int* __restrict__ src, const int* __restrict__ dst,
                       const float4* __restrict__ x4) {
    int i = blockIdx.x * blockDim.x + threadIdx.x;
    if (i >= NE * (INF / 4)) return;
    int e = i / (INF / 4);
    int j = i - e * (INF / 4);
    int s = src[e], d = dst[e];          // 24 consecutive threads share e -> broadcast loads
    float ns = g_nout[s];
    float4 v = x4[s * (INF / 4) + j];
    v.x *= ns; v.y *= ns; v.z *= ns; v.w *= ns;
    red_add_v4(((float4*)g_agg1) + d * (INF / 4) + j, v);
}

// g_h = relu( (agg1 * nin[row]) @ W1 + b1 ) * nout[row]
// tiled SGEMM: BM=64 BN=64 BK=16, 256 threads, 4x4 micro-tile
__global__ void k_gemm1(const float* __restrict__ W1, const float* __restrict__ b1) {
    __shared__ float As[16][64];
    __shared__ float Bs[16][64];
    int tid = threadIdx.x;
    int tx = tid & 15, ty = tid >> 4;
    int rowBase = blockIdx.x * 64;
    int colBase = blockIdx.y * 64;
    float acc[4][4] = {};
    for (int kk = 0; kk < INF; kk += 16) {
        #pragma unroll
        for (int l = 0; l < 4; l++) {                     // A tile 64x16
            int lid = tid + l * 256;
            int r = lid >> 4, k = lid & 15;
            int gr = rowBase + r;
            As[k][r] = (gr < NN) ? g_agg1[gr * INF + kk + k] : 0.f;
        }
        #pragma unroll
        for (int l = 0; l < 4; l++) {                     // B tile 16x64
            int lid = tid + l * 256;
            int k = lid >> 6, n = lid & 63;
            Bs[k][n] = W1[(kk + k) * HF + colBase + n];
        }
        __syncthreads();
        #pragma unroll
        for (int k = 0; k < 16; k++) {
            float a[4], b[4];
            #pragma unroll
            for (int i = 0; i < 4; i++) a[i] = As[k][ty * 4 + i];
            #pragma unroll
            for (int j = 0; j < 4; j++) b[j] = Bs[k][tx * 4 + j];
            #pragma unroll
            for (int i = 0; i < 4; i++)
                #pragma unroll
                for (int j = 0; j < 4; j++)
                    acc[i][j] = fmaf(a[i], b[j], acc[i][j]);
        }
        __syncthreads();
    }
    #pragma unroll
    for (int i = 0; i < 4; i++) {
        int row = rowBase + ty * 4 + i;
        if (row >= NN) continue;
        float nin = g_nin[row], nout = g_nout[row];
        #pragma unroll
        for (int j = 0; j < 4; j++) {
            int col = colBase + tx * 4 + j;
            float v = fmaf(acc[i][j], nin, b1[col]);   // (agg*nin)@W1 + b1
            g_h[row * HF + col] = fmaxf(v, 0.f) * nout;
        }
    }
}

// g_p = g_h @ W2   (M=50000, K=256, N=40); BM=64 BK=32, 256 thr, 2x5 micro-tile
__global__ void k_gemm2(const float* __restrict__ W2) {
    __shared__ float As[32][64];
    __shared__ float Bs[32][40];
    int tid = threadIdx.x;
    int tx = tid & 7, ty = tid >> 3;       // tx: 8 col-groups of 5; ty: 32 row-pairs
    int rowBase = blockIdx.x * 64;
    float acc[2][5] = {};
    for (int kk = 0; kk < HF; kk += 32) {
        #pragma unroll
        for (int l = 0; l < 8; l++) {                    // A tile 64x32
            int lid = tid + l * 256;
            int r = lid >> 5, k = lid & 31;
            int gr = rowBase + r;
            As[k][r] = (gr < NN) ? g_h[gr * HF + kk + k] : 0.f;
        }
        #pragma unroll
        for (int l = 0; l < 5; l++) {                    // B tile 32x40
            int lid = tid + l * 256;
            int k = lid / 40, n = lid - k * 40;
            Bs[k][n] = W2[(kk + k) * NC + n];
        }
        __syncthreads();
        #pragma unroll
        for (int k = 0; k < 32; k++) {
            float a0 = As[k][ty * 2], a1 = As[k][ty * 2 + 1];
            #pragma unroll
            for (int j = 0; j < 5; j++) {
                float b = Bs[k][tx * 5 + j];
                acc[0][j] = fmaf(a0, b, acc[0][j]);
                acc[1][j] = fmaf(a1, b, acc[1][j]);
            }
        }
        __syncthreads();
    }
    #pragma unroll
    for (int i = 0; i < 2; i++) {
        int row = rowBase + ty * 2 + i;
        if (row >= NN) continue;
        #pragma unroll
        for (int j = 0; j < 5; j++)
            g_p[row * NC + tx * 5 + j] = acc[i][j];
    }
}

// layer-2 aggregation: for each (edge, float4-chunk): out[dst] += p[src]
__global__ void k_agg2(const int* __restrict__ src, const int* __restrict__ dst,
                       float4* __restrict__ out4) {
    int i = blockIdx.x * blockDim.x + threadIdx.x;
    if (i >= NE * (NC / 4)) return;
    int e = i / (NC / 4);
    int j = i - e * (NC / 4);
    int s = src[e], d = dst[e];
    float4 v = ((const float4*)g_p)[s * (NC / 4) + j];
    red_add_v4(out4 + d * (NC / 4) + j, v);
}

// out = out * nin[row] + b2
__global__ void k_final(float4* __restrict__ out4, const float4* __restrict__ b2_4) {
    int i = blockIdx.x * blockDim.x + threadIdx.x;
    if (i < NN * (NC / 4)) {
        int row = i / (NC / 4);
        int c = i - row * (NC / 4);
        float s = g_nin[row];
        float4 v = out4[i];
        float4 b = b2_4[c];
        v.x = fmaf(v.x, s, b.x);
        v.y = fmaf(v.y, s, b.y);
        v.z = fmaf(v.z, s, b.z);
        v.w = fmaf(v.w, s, b.w);
        out4[i] = v;
    }
}

// ---------------- launch ----------------
extern "C" void kernel_launch(void* const* d_in, const int* in_sizes, int n_in,
                              void* d_out, int out_size) {
    const float* x  = (const float*)d_in[0];
    const int*   src = (const int*)d_in[1];
    const int*   dst = (const int*)d_in[2];
    const float* W1 = (const float*)d_in[3];
    const float* b1 = (const float*)d_in[4];
    const float* W2 = (const float*)d_in[5];
    const float* b2 = (const float*)d_in[6];
    float* out = (float*)d_out;
    (void)in_sizes; (void)n_in; (void)out_size;

    k_zero<<<2048, 256>>>((float4*)out);
    k_deg<<<(NE + 255) / 256, 256>>>(src, dst);
    k_norm<<<(NN + 255) / 256, 256>>>();
    k_agg1<<<NE * (INF / 4) / 256, 256>>>(src, dst, (const float4*)x);
    k_gemm1<<<dim3((NN + 63) / 64, HF / 64), 256>>>(W1, b1);
    k_gemm2<<<(NN + 63) / 64, 256>>>(W2);
    k_agg2<<<NE * (NC / 4) / 256, 256>>>(src, dst, (float4*)out);
    k_final<<<(NN * (NC / 4) + 255) / 256, 256>>>((float4*)out, (const float4*)b2);
}

// round 9
// speedup vs baseline: 1.1046x; 1.1046x over previous
#include <cuda_runtime.h>

#define NN 50000
#define NE 800000
#define INF 96
#define HF  256
#define NC  40
#define CHUNK 512
#define NCHUNK ((NN + CHUNK - 1) / CHUNK)   // 98

// ---------------- scratch (__device__ globals; no allocations) ----------------
__device__ int   g_dego_i[NN];    // out-degree (int)
__device__ int   g_degi_i[NN];    // in-degree  (int)
__device__ float g_nout[NN];      // rsqrt(max(deg_out,1))
__device__ float g_nin[NN];       // rsqrt(max(deg_in,1))
__device__ int   g_local[NN];     // per-chunk exclusive scan of in-degree
__device__ int   g_chunksum[NCHUNK];
__device__ int   g_chunkbase[NCHUNK];
__device__ int   g_rowstart[NN];  // CSR row offsets (by dst)
__device__ int   g_cursor[NN];    // fill cursors
__device__ int   g_eidx[NE];      // CSR payload: src node id per slot
__device__ __align__(16) float g_agg1[NN * INF];  // edge-aggregated x*nout
__device__ __align__(16) float g_h[NN * HF];      // relu(layer1)*nout
__device__ __align__(16) float g_p[NN * NC];      // g_h @ W2

// ---------------- CSR build ----------------

__global__ void k_zero() {
    int i = blockIdx.x * blockDim.x + threadIdx.x;
    if (i < NN) { g_dego_i[i] = 0; g_degi_i[i] = 0; }
}

__global__ void k_count(const int* __restrict__ src, const int* __restrict__ dst) {
    int e = blockIdx.x * blockDim.x + threadIdx.x;
    if (e < NE) {
        atomicAdd(&g_dego_i[src[e]], 1);
        atomicAdd(&g_degi_i[dst[e]], 1);
    }
}

__global__ void k_norm() {
    int i = blockIdx.x * blockDim.x + threadIdx.x;
    if (i < NN) {
        g_nout[i] = rsqrtf(fmaxf((float)g_dego_i[i], 1.f));
        g_nin[i]  = rsqrtf(fmaxf((float)g_degi_i[i], 1.f));
    }
}

// per-chunk inclusive scan of in-degrees; writes exclusive local offsets + chunk totals
__global__ void k_scan_chunk() {
    __shared__ int sh[CHUNK];
    int i = blockIdx.x * CHUNK + threadIdx.x;
    int v = (i < NN) ? g_degi_i[i] : 0;
    sh[threadIdx.x] = v;
    __syncthreads();
    for (int off = 1; off < CHUNK; off <<= 1) {
        int t = (threadIdx.x >= off) ? sh[threadIdx.x - off] : 0;
        __syncthreads();
        sh[threadIdx.x] += t;
        __syncthreads();
    }
    int incl = sh[threadIdx.x];
    if (i < NN) g_local[i] = incl - v;
    if (threadIdx.x == CHUNK - 1) g_chunksum[blockIdx.x] = incl;
}

// single-block scan of chunk totals -> exclusive chunk bases
__global__ void k_scan_top() {
    __shared__ int sh[128];
    int t = threadIdx.x;
    int v = (t < NCHUNK) ? g_chunksum[t] : 0;
    sh[t] = v;
    __syncthreads();
    for (int off = 1; off < 128; off <<= 1) {
        int u = (t >= off) ? sh[t - off] : 0;
        __syncthreads();
        sh[t] += u;
        __syncthreads();
    }
    if (t < NCHUNK) g_chunkbase[t] = sh[t] - v;
}

__global__ void k_setcur() {
    int i = blockIdx.x * blockDim.x + threadIdx.x;
    if (i < NN) {
        int base = g_chunkbase[i / CHUNK] + g_local[i];
        g_rowstart[i] = base;
        g_cursor[i] = base;
    }
}

__global__ void k_fill(const int* __restrict__ src, const int* __restrict__ dst) {
    int e = blockIdx.x * blockDim.x + threadIdx.x;
    if (e < NE) {
        int pos = atomicAdd(&g_cursor[dst[e]], 1);
        g_eidx[pos] = src[e];
    }
}

// ---------------- aggregations (gather-only, warp per dst row) ----------------

// agg1[d] = sum over edges into d of x[s] * nout[s]; 96 floats -> 3 per lane
// 2-edge unroll for memory-level parallelism on the eidx->x dependent chain.
__global__ void k_agg1_csr(const float* __restrict__ x) {
    int w = (blockIdx.x * blockDim.x + threadIdx.x) >> 5;
    if (w >= NN) return;
    int lane = threadIdx.x & 31;
    int beg = g_rowstart[w], end = beg + g_degi_i[w];
    float a0 = 0.f, a1 = 0.f, a2 = 0.f;
    int p = beg;
    for (; p + 2 <= end; p += 2) {
        int s0 = __ldg(&g_eidx[p]);
        int s1 = __ldg(&g_eidx[p + 1]);
        float n0 = __ldg(&g_nout[s0]);
        float n1 = __ldg(&g_nout[s1]);
        const float* x0 = x + s0 * INF;
        const float* x1 = x + s1 * INF;
        float v00 = __ldg(x0 + lane), v01 = __ldg(x0 + lane + 32), v02 = __ldg(x0 + lane + 64);
        float v10 = __ldg(x1 + lane), v11 = __ldg(x1 + lane + 32), v12 = __ldg(x1 + lane + 64);
        a0 = fmaf(v00, n0, a0); a1 = fmaf(v01, n0, a1); a2 = fmaf(v02, n0, a2);
        a0 = fmaf(v10, n1, a0); a1 = fmaf(v11, n1, a1); a2 = fmaf(v12, n1, a2);
    }
    if (p < end) {
        int s = __ldg(&g_eidx[p]);
        float ns = __ldg(&g_nout[s]);
        const float* xr = x + s * INF;
        a0 = fmaf(__ldg(xr + lane),      ns, a0);
        a1 = fmaf(__ldg(xr + lane + 32), ns, a1);
        a2 = fmaf(__ldg(xr + lane + 64), ns, a2);
    }
    float* o = g_agg1 + w * INF;
    o[lane] = a0; o[lane + 32] = a1; o[lane + 64] = a2;
}

// out[d] = (sum over edges into d of p[s]) * nin[d] + b2;  40 floats/row
__global__ void k_agg2_csr(float* __restrict__ out, const float* __restrict__ b2) {
    int w = (blockIdx.x * blockDim.x + threadIdx.x) >> 5;
    if (w >= NN) return;
    int lane = threadIdx.x & 31;
    int beg = g_rowstart[w], end = beg + g_degi_i[w];
    float a0 = 0.f, a1 = 0.f;
    int p = beg;
    for (; p + 2 <= end; p += 2) {
        int s0 = __ldg(&g_eidx[p]);
        int s1 = __ldg(&g_eidx[p + 1]);
        const float* p0 = g_p + s0 * NC;
        const float* p1 = g_p + s1 * NC;
        float u0 = __ldg(p0 + lane);
        float u1 = __ldg(p1 + lane);
        a0 += u0 + u1;
        if (lane < 8) {
            float w0 = __ldg(p0 + lane + 32);
            float w1 = __ldg(p1 + lane + 32);
            a1 += w0 + w1;
        }
    }
    if (p < end) {
        int s = __ldg(&g_eidx[p]);
        const float* pr = g_p + s * NC;
        a0 += __ldg(pr + lane);
        if (lane < 8) a1 += __ldg(pr + lane + 32);
    }
    float sc = g_nin[w];
    float* o = out + w * NC;
    o[lane] = fmaf(a0, sc, b2[lane]);
    if (lane < 8) o[lane + 32] = fmaf(a1, sc, b2[lane + 32]);
}

// ---------------- GEMMs (unchanged from round 4) ----------------

// g_h = relu( (agg1 * nin[row]) @ W1 + b1 ) * nout[row]
__global__ void k_gemm1(const float* __restrict__ W1, const float* __restrict__ b1) {
    __shared__ float As[16][64];
    __shared__ float Bs[16][64];
    int tid = threadIdx.x;
    int tx = tid & 15, ty = tid >> 4;
    int rowBase = blockIdx.x * 64;
    int colBase = blockIdx.y * 64;
    float acc[4][4] = {};
    for (int kk = 0; kk < INF; kk += 16) {
        #pragma unroll
        for (int l = 0; l < 4; l++) {
            int lid = tid + l * 256;
            int r = lid >> 4, k = lid & 15;
            int gr = rowBase + r;
            As[k][r] = (gr < NN) ? g_agg1[gr * INF + kk + k] : 0.f;
        }
        #pragma unroll
        for (int l = 0; l < 4; l++) {
            int lid = tid + l * 256;
            int k = lid >> 6, n = lid & 63;
            Bs[k][n] = W1[(kk + k) * HF + colBase + n];
        }
        __syncthreads();
        #pragma unroll
        for (int k = 0; k < 16; k++) {
            float a[4], b[4];
            #pragma unroll
            for (int i = 0; i < 4; i++) a[i] = As[k][ty * 4 + i];
            #pragma unroll
            for (int j = 0; j < 4; j++) b[j] = Bs[k][tx * 4 + j];
            #pragma unroll
            for (int i = 0; i < 4; i++)
                #pragma unroll
                for (int j = 0; j < 4; j++)
                    acc[i][j] = fmaf(a[i], b[j], acc[i][j]);
        }
        __syncthreads();
    }
    #pragma unroll
    for (int i = 0; i < 4; i++) {
        int row = rowBase + ty * 4 + i;
        if (row >= NN) continue;
        float nin = g_nin[row], nout = g_nout[row];
        #pragma unroll
        for (int j = 0; j < 4; j++) {
            int col = colBase + tx * 4 + j;
            float v = fmaf(acc[i][j], nin, b1[col]);
            g_h[row * HF + col] = fmaxf(v, 0.f) * nout;
        }
    }
}

// g_p = g_h @ W2
__global__ void k_gemm2(const float* __restrict__ W2) {
    __shared__ float As[32][64];
    __shared__ float Bs[32][40];
    int tid = threadIdx.x;
    int tx = tid & 7, ty = tid >> 3;
    int rowBase = blockIdx.x * 64;
    float acc[2][5] = {};
    for (int kk = 0; kk < HF; kk += 32) {
        #pragma unroll
        for (int l = 0; l < 8; l++) {
            int lid = tid + l * 256;
            int r = lid >> 5, k = lid & 31;
            int gr = rowBase + r;
            As[k][r] = (gr < NN) ? g_h[gr * HF + kk + k] : 0.f;
        }
        #pragma unroll
        for (int l = 0; l < 5; l++) {
            int lid = tid + l * 256;
            int k = lid / 40, n = lid - k * 40;
            Bs[k][n] = W2[(kk + k) * NC + n];
        }
        __syncthreads();
        #pragma unroll
        for (int k = 0; k < 32; k++) {
            float a0 = As[k][ty * 2], a1 = As[k][ty * 2 + 1];
            #pragma unroll
            for (int j = 0; j < 5; j++) {
                float b = Bs[k][tx * 5 + j];
                acc[0][j] = fmaf(a0, b, acc[0][j]);
                acc[1][j] = fmaf(a1, b, acc[1][j]);
            }
        }
        __syncthreads();
    }
    #pragma unroll
    for (int i = 0; i < 2; i++) {
        int row = rowBase + ty * 2 + i;
        if (row >= NN) continue;
        #pragma unroll
        for (int j = 0; j < 5; j++)
            g_p[row * NC + tx * 5 + j] = acc[i][j];
    }
}

// ---------------- launch ----------------
extern "C" void kernel_launch(void* const* d_in, const int* in_sizes, int n_in,
                              void* d_out, int out_size) {
    const float* x  = (const float*)d_in[0];
    const int*   src = (const int*)d_in[1];
    const int*   dst = (const int*)d_in[2];
    const float* W1 = (const float*)d_in[3];
    const float* b1 = (const float*)d_in[4];
    const float* W2 = (const float*)d_in[5];
    const float* b2 = (const float*)d_in[6];
    float* out = (float*)d_out;
    (void)in_sizes; (void)n_in; (void)out_size;

    // CSR build
    k_zero<<<(NN + 255) / 256, 256>>>();
    k_count<<<(NE + 255) / 256, 256>>>(src, dst);
    k_norm<<<(NN + 255) / 256, 256>>>();
    k_scan_chunk<<<NCHUNK, CHUNK>>>();
    k_scan_top<<<1, 128>>>();
    k_setcur<<<(NN + 255) / 256, 256>>>();
    k_fill<<<(NE + 255) / 256, 256>>>(src, dst);

    // layer 1
    k_agg1_csr<<<(NN * 32 + 255) / 256, 256>>>(x);
    k_gemm1<<<dim3((NN + 63) / 64, HF / 64), 256>>>(W1, b1);

    // layer 2
    k_gemm2<<<(NN + 63) / 64, 256>>>(W2);
    k_agg2_csr<<<(NN * 32 + 255) / 256, 256>>>(out, b2);
}